// round 11
// baseline (speedup 1.0000x reference)
#include <cuda_runtime.h>

#define T_STEPS 4096
#define NCTA    128
#define NTHR    256

typedef unsigned long long ull;

// ---------------- global scratch (static; no allocs) ----------------
// h layout: [slot][mpair 0..127][b 0..63][2] -> element (m,b) at [m>>1][b][m&1]
__device__ __align__(256) float g_h0[2][128][64][2];     // h0(s) at slot s&1
__device__ __align__(256) float g_h1[4098][128][64][2];  // h1(s) at slot s+2; slots 0,1 zero
__device__ __align__(256) float g_yT[4099][64];          // yT[t+3][b] = y[b][t]; rows 0..2 pad
__device__ unsigned g_cnt;    // zero-init; reset to 0 each barrier
__device__ unsigned g_sense;  // zero-init; even total rounds (4098) -> returns to 0

// ---------------- helpers ----------------
__device__ __forceinline__ ull ffma2(ull h, ull w, ull a) {
    ull d;
    asm("fma.rn.f32x2 %0, %1, %2, %3;" : "=l"(d) : "l"(h), "l"(w), "l"(a));
    return d;
}
__device__ __forceinline__ float collapse2(ull a) {   // sum of the two packed lanes
    return __uint_as_float((unsigned)a) + __uint_as_float((unsigned)(a >> 32));
}
__device__ __forceinline__ float sigf(float x)   { return 1.0f / (1.0f + __expf(-x)); }
__device__ __forceinline__ float tanh_f(float x) { return 2.0f * sigf(2.0f * x) - 1.0f; }

__device__ __forceinline__ ull ldcg1(const float* p) {
    ull v;
    asm volatile("ld.global.cg.u64 %0, [%1];" : "=l"(v) : "l"(p));
    return v;
}
__device__ __forceinline__ unsigned atom_add_acqrel(unsigned* p, unsigned v) {
    unsigned old;
    asm volatile("atom.acq_rel.gpu.global.add.u32 %0, [%1], %2;"
                 : "=r"(old) : "l"(p), "r"(v) : "memory");
    return old;
}
__device__ __forceinline__ unsigned ld_acquire(const unsigned* p) {
    unsigned v;
    asm volatile("ld.acquire.gpu.global.u32 %0, [%1];" : "=r"(v) : "l"(p) : "memory");
    return v;
}
__device__ __forceinline__ void st_release(unsigned* p, unsigned v) {
    asm volatile("st.release.gpu.global.u32 [%0], %1;" :: "l"(p), "r"(v) : "memory");
}
__device__ __forceinline__ void st_relaxed(unsigned* p, unsigned v) {
    asm volatile("st.relaxed.gpu.global.u32 [%0], %1;" :: "l"(p), "r"(v) : "memory");
}

// self-resetting sense-reversing grid barrier; only tid 0 polls.
__device__ __forceinline__ void grid_barrier(int tid, unsigned& ls) {
    __syncthreads();
    ls ^= 1u;
    if (tid == 0) {
        unsigned old = atom_add_acqrel(&g_cnt, 1u);
        if (old == NCTA - 1u) {
            st_relaxed(&g_cnt, 0u);
            st_release(&g_sense, ls);
        } else {
            while (ld_acquire(&g_sense) != ls) { }
        }
    }
    __syncthreads();
}

// ---------------- smem layout (floats) ----------------
//   W0s [32][256] @ 0      (8192)   W_hh0 rows (plain fp32, K-major)
//   W1s [32][256] @ 8192   (8192)   W_ih1
//   WHs [32][256] @ 16384  (8192)   W_hh1
//   P0  [16][32][16] @ 24576 (8192) layer0 gate partials (q, lr, local batch)
//   P1  [16][32][16] @ 32768 (8192)
//   misc @ 40960: wih0[32][4]=128, b0s[32], b1s[32], yw[4][16]=64, wout[512], bo2[2]
#define SMEM_FLOATS (40960 + 832)
#define SMEM_BYTES  (SMEM_FLOATS * 4)

__global__ void __launch_bounds__(NTHR, 1) lstm_all(
    const float* __restrict__ y,
    const float* __restrict__ Wih0, const float* __restrict__ Whh0,
    const float* __restrict__ bih0, const float* __restrict__ bhh0,
    const float* __restrict__ Wih1, const float* __restrict__ Whh1,
    const float* __restrict__ bih1, const float* __restrict__ bhh1,
    const float* __restrict__ Wout, const float* __restrict__ bout,
    float* __restrict__ out)
{
    extern __shared__ float sm[];
    float* W0s  = sm;              // [32][256]
    float* W1s  = sm + 8192;       // [32][256]
    float* WHs  = sm + 16384;      // [32][256]
    float* P0   = sm + 24576;      // [16][32][16]
    float* P1   = sm + 32768;      // [16][32][16]
    float* wih0 = sm + 40960;      // [32][4]
    float* b0s  = wih0 + 128;      // [32]
    float* b1s  = b0s + 32;        // [32]
    float* yw   = b1s + 32;        // [4][16]
    float* wout = yw + 64;         // [2][256]
    float* bo2  = wout + 512;      // [2]

    const int tid = threadIdx.x;
    const int bid = blockIdx.x;
    const int rg  = bid >> 2;            // 32 row-groups
    const int bg  = bid & 3;             // 4 batch-groups
    const int j0  = rg * 8;              // CTA owns hidden units j0..j0+7
    const int b0  = bg * 16;             // CTA owns batches b0..b0+15
    unsigned ls = 0;

    // ======== init: global state ========
    {
        int gi = bid * NTHR + tid;       // 0..32767
        ((float*)g_h0)[gi] = 0.0f;       // both h0 slots (2*128*64*2 = 32768)
        ((float*)g_h1)[gi] = 0.0f;       // h1 slots 0,1 (2*16384 = 32768)
        for (int i = gi; i < 4099 * 64; i += NCTA * NTHR) {
            int row = i >> 6, b = i & 63;
            g_yT[row][b] = (row < 3) ? -100.0f : y[b * T_STEPS + (row - 3)];
        }
    }

    // ======== init: smem weights (plain fp32, K-major rows) ========
    // local row lr = gate*8 + u ; global row = gate*256 + j0 + u
    for (int idx = tid; idx < 32 * 256; idx += NTHR) {
        int lr = idx >> 8, m = idx & 255;
        int row = (lr >> 3) * 256 + j0 + (lr & 7);
        W0s[idx] = Whh0[row * 256 + m];
        W1s[idx] = Wih1[row * 256 + m];
        WHs[idx] = Whh1[row * 256 + m];
    }
    if (tid < 32) {
        int row = (tid >> 3) * 256 + j0 + (tid & 7);
        b0s[tid] = bih0[row] + bhh0[row];
        b1s[tid] = bih1[row] + bhh1[row];
        for (int k = 0; k < 4; k++) wih0[tid * 4 + k] = Wih0[row * 4 + k];
    }
    wout[tid] = Wout[tid];
    wout[256 + tid] = Wout[256 + tid];
    if (tid < 2) bo2[tid] = bout[tid];
    grid_barrier(tid, ls);   // round 1

    // ======== persistent 2-layer LSTM ========
    const int q  = tid >> 4;             // m-chunk (16 chunks of 16 m); warp has 2 q
    const int tb = tid & 15;             // local batch
    const int bb = b0 + tb;              // global batch
    const int hoff = q * 8 * 128 + bb * 2;   // float offset of first K-pair

    // cell-update role (fixed per thread; c lives in a register)
    const int cu   = (tid >> 4) & 7;     // unit 0..7
    const int clb  = tid & 15;           // local batch
    const int chalf = tid >> 7;          // 0: layer0 cell, 1: layer1 cell
    float creg = 0.0f;

    for (int p = 0; p <= T_STEPS; p++) {
        const float* H0 = &g_h0[(p + 1) & 1][0][0][0] + hoff;  // h0(p-1)
        const float* H1 = &g_h1[p][0][0][0] + hoff;            // h1(p-2)
        if (tid < 64 && p < T_STEPS) yw[tid] = g_yT[p + (tid >> 4)][b0 + (tid & 15)];

        ull h0p[8], h1p[8];
        #pragma unroll
        for (int i = 0; i < 8; i++) h0p[i] = ldcg1(H0 + i * 128);
        #pragma unroll
        for (int i = 0; i < 8; i++) h1p[i] = ldcg1(H1 + i * 128);

        // ---- layer0: 32 rows x thread's 16 m x 1 batch ----
        {
            ull acc[32];
            #pragma unroll
            for (int lr = 0; lr < 32; lr++) acc[lr] = 0ull;
            #pragma unroll
            for (int i2 = 0; i2 < 4; i2++) {
                const ull hA = h0p[2 * i2], hB = h0p[2 * i2 + 1];
                const float* wp = W0s + q * 16 + i2 * 4;
                #pragma unroll
                for (int lr = 0; lr < 32; lr++) {
                    ulonglong2 w = *(const ulonglong2*)(wp + lr * 256);
                    acc[lr] = ffma2(hA, w.x, acc[lr]);
                    acc[lr] = ffma2(hB, w.y, acc[lr]);
                }
            }
            #pragma unroll
            for (int lr = 0; lr < 32; lr++)
                P0[q * 512 + lr * 16 + tb] = collapse2(acc[lr]);
        }
        // ---- layer1: W_ih1 x h0(p-1) + W_hh1 x h1(p-2) ----
        {
            ull acc[32];
            #pragma unroll
            for (int lr = 0; lr < 32; lr++) acc[lr] = 0ull;
            #pragma unroll
            for (int i2 = 0; i2 < 4; i2++) {
                const ull hA = h0p[2 * i2], hB = h0p[2 * i2 + 1];
                const float* wp = W1s + q * 16 + i2 * 4;
                #pragma unroll
                for (int lr = 0; lr < 32; lr++) {
                    ulonglong2 w = *(const ulonglong2*)(wp + lr * 256);
                    acc[lr] = ffma2(hA, w.x, acc[lr]);
                    acc[lr] = ffma2(hB, w.y, acc[lr]);
                }
            }
            #pragma unroll
            for (int i2 = 0; i2 < 4; i2++) {
                const ull hA = h1p[2 * i2], hB = h1p[2 * i2 + 1];
                const float* wp = WHs + q * 16 + i2 * 4;
                #pragma unroll
                for (int lr = 0; lr < 32; lr++) {
                    ulonglong2 w = *(const ulonglong2*)(wp + lr * 256);
                    acc[lr] = ffma2(hA, w.x, acc[lr]);
                    acc[lr] = ffma2(hB, w.y, acc[lr]);
                }
            }
            #pragma unroll
            for (int lr = 0; lr < 32; lr++)
                P1[q * 512 + lr * 16 + tb] = collapse2(acc[lr]);
        }
        __syncthreads();

        // ---- reduce 16 q-partials, cell update, publish h ----
        {
            const bool act = chalf ? (p > 0) : (p < T_STEPS);
            if (act) {
                const float* P  = chalf ? P1 : P0;
                const float* bs = chalf ? b1s : b0s;
                float gg[4];
                #pragma unroll
                for (int gt = 0; gt < 4; gt++) {
                    int lr = gt * 8 + cu;
                    float s = bs[lr];
                    #pragma unroll
                    for (int qq = 0; qq < 16; qq++)
                        s += P[qq * 512 + lr * 16 + clb];
                    gg[gt] = s;
                }
                if (chalf == 0) {
                    #pragma unroll
                    for (int gt = 0; gt < 4; gt++) {
                        int lr = gt * 8 + cu;
                        #pragma unroll
                        for (int k = 0; k < 4; k++)
                            gg[gt] = fmaf(yw[k * 16 + clb], wih0[lr * 4 + k], gg[gt]);
                    }
                }
                creg = sigf(gg[1]) * creg + sigf(gg[0]) * tanh_f(gg[2]);
                float h = sigf(gg[3]) * tanh_f(creg);
                int j = j0 + cu, b = b0 + clb;
                if (chalf == 0) g_h0[p & 1][j >> 1][b][j & 1] = h;   // h0(p)
                else            g_h1[p + 1][j >> 1][b][j & 1] = h;   // h1(p-1)
            }
        }
        grid_barrier(tid, ls);   // rounds 2..4098 (even total)
    }

    // ======== output projection: out[b][t][k] = h1(t).Wout[k] + bout[k] ========
    {
        const int b  = tid & 63;
        const int tt = tid >> 6;    // 0..3
        #pragma unroll
        for (int u = 0; u < 8; u++) {
            int t = bid * 32 + tt * 8 + u;
            const float* h = &g_h1[t + 2][0][0][0] + b * 2;
            float s0 = bo2[0], s1 = bo2[1];
            #pragma unroll 8
            for (int mp = 0; mp < 128; mp++) {
                ull v = ldcg1(h + mp * 128);
                float ve = __uint_as_float((unsigned)v);
                float vo = __uint_as_float((unsigned)(v >> 32));
                s0 = fmaf(ve, wout[2 * mp],       s0);
                s0 = fmaf(vo, wout[2 * mp + 1],   s0);
                s1 = fmaf(ve, wout[256 + 2 * mp], s1);
                s1 = fmaf(vo, wout[257 + 2 * mp], s1);
            }
            out[b * (T_STEPS * 2) + t * 2 + 0] = s0;
            out[b * (T_STEPS * 2) + t * 2 + 1] = s1;
        }
    }
}

// ---------------- launcher: ONE kernel ----------------
extern "C" void kernel_launch(void* const* d_in, const int* in_sizes, int n_in,
                              void* d_out, int out_size)
{
    (void)in_sizes; (void)n_in; (void)out_size;
    cudaFuncSetAttribute(lstm_all, cudaFuncAttributeMaxDynamicSharedMemorySize, SMEM_BYTES);
    lstm_all<<<NCTA, NTHR, SMEM_BYTES>>>(
        (const float*)d_in[0],
        (const float*)d_in[1], (const float*)d_in[2],
        (const float*)d_in[3], (const float*)d_in[4],
        (const float*)d_in[5], (const float*)d_in[6],
        (const float*)d_in[7], (const float*)d_in[8],
        (const float*)d_in[9], (const float*)d_in[10],
        (float*)d_out);
}

// round 12
// speedup vs baseline: 1.2170x; 1.2170x over previous
#include <cuda_runtime.h>

#define T_STEPS 4096
#define NCTA    128
#define NTHR    512

typedef unsigned long long ull;

// ---------------- global scratch (static; no allocs) ----------------
// h layout: [slot][mpair 0..127][b 0..63][2] -> element (m,b) at [m>>1][b][m&1]
__device__ __align__(256) float g_h0[2][128][64][2];     // h0(s) at slot s&1
__device__ __align__(256) float g_h1[4098][128][64][2];  // h1(s) at slot s+2; slots 0,1 zero
__device__ __align__(256) float g_yT[4099][64];          // yT[t+3][b] = y[b][t]; rows 0..2 pad
__device__ unsigned g_cnt;    // zero-init; reset to 0 each barrier
__device__ unsigned g_sense;  // zero-init; even total rounds (4098) -> returns to 0

// ---------------- helpers ----------------
__device__ __forceinline__ ull ffma2(ull h, ull w, ull a) {
    ull d;
    asm("fma.rn.f32x2 %0, %1, %2, %3;" : "=l"(d) : "l"(h), "l"(w), "l"(a));
    return d;
}
__device__ __forceinline__ float collapse2(ull a) {   // even-m sum + odd-m sum
    return __uint_as_float((unsigned)a) + __uint_as_float((unsigned)(a >> 32));
}
__device__ __forceinline__ float sigf(float x)   { return 1.0f / (1.0f + __expf(-x)); }
__device__ __forceinline__ float tanh_f(float x) { return 2.0f * sigf(2.0f * x) - 1.0f; }

__device__ __forceinline__ ulonglong2 ldcg2(const float* p) {
    ulonglong2 v;
    asm volatile("ld.global.cg.v2.u64 {%0,%1}, [%2];" : "=l"(v.x), "=l"(v.y) : "l"(p));
    return v;
}
__device__ __forceinline__ unsigned atom_add_acqrel(unsigned* p, unsigned v) {
    unsigned old;
    asm volatile("atom.acq_rel.gpu.global.add.u32 %0, [%1], %2;"
                 : "=r"(old) : "l"(p), "r"(v) : "memory");
    return old;
}
__device__ __forceinline__ unsigned ld_acquire(const unsigned* p) {
    unsigned v;
    asm volatile("ld.acquire.gpu.global.u32 %0, [%1];" : "=r"(v) : "l"(p) : "memory");
    return v;
}
__device__ __forceinline__ void st_release(unsigned* p, unsigned v) {
    asm volatile("st.release.gpu.global.u32 [%0], %1;" :: "l"(p), "r"(v) : "memory");
}
__device__ __forceinline__ void st_relaxed(unsigned* p, unsigned v) {
    asm volatile("st.relaxed.gpu.global.u32 [%0], %1;" :: "l"(p), "r"(v) : "memory");
}

// self-resetting sense-reversing grid barrier; only tid 0 polls.
__device__ __forceinline__ void grid_barrier(int tid, unsigned& ls) {
    __syncthreads();
    ls ^= 1u;
    if (tid == 0) {
        unsigned old = atom_add_acqrel(&g_cnt, 1u);
        if (old == NCTA - 1u) {
            st_relaxed(&g_cnt, 0u);
            st_release(&g_sense, ls);
        } else {
            while (ld_acquire(&g_sense) != ls) { }
        }
    }
    __syncthreads();
}

// ---------------- smem layout (floats) ----------------
//   W0s [8][256]    @ 0      (2048)  W_hh0 rows, plain fp32 K-major
//   W1s [8][256]    @ 2048   (2048)  W_ih1
//   WHs [8][256]    @ 4096   (2048)  W_hh1
//   P0  [16][8][64] @ 6144   (8192)  layer0 gate partials (q, row, batch)
//   P1  [16][8][64] @ 14336  (8192)
//   misc @ 22528: wih0[8][4]=32, b0s[8], b1s[8], yw[4][64]=256, wout[512], bo2[2]
#define SMEM_FLOATS (22528 + 818)
#define SMEM_BYTES  (SMEM_FLOATS * 4)

__global__ void __launch_bounds__(NTHR, 1) lstm_all(
    const float* __restrict__ y,
    const float* __restrict__ Wih0, const float* __restrict__ Whh0,
    const float* __restrict__ bih0, const float* __restrict__ bhh0,
    const float* __restrict__ Wih1, const float* __restrict__ Whh1,
    const float* __restrict__ bih1, const float* __restrict__ bhh1,
    const float* __restrict__ Wout, const float* __restrict__ bout,
    float* __restrict__ out)
{
    extern __shared__ float sm[];
    float* W0s  = sm;              // [8][256]
    float* W1s  = sm + 2048;       // [8][256]
    float* WHs  = sm + 4096;       // [8][256]
    float* P0   = sm + 6144;       // [16][8][64]
    float* P1   = sm + 14336;      // [16][8][64]
    float* wih0 = sm + 22528;      // [8][4]
    float* b0s  = wih0 + 32;       // [8]
    float* b1s  = b0s + 8;         // [8]
    float* yw   = b1s + 8;         // [4][64]
    float* wout = yw + 256;        // [2][256]
    float* bo2  = wout + 512;      // [2]

    const int tid = threadIdx.x;
    const int bid = blockIdx.x;
    const int j0  = bid * 2;                 // CTA owns hidden units j0, j0+1
    unsigned ls = 0;

    // ======== init: global state ========
    {
        int gi = bid * NTHR + tid;           // 0..65535
        if (gi < 32768) {
            ((float*)g_h0)[gi] = 0.0f;       // both h0 slots
            ((float*)g_h1)[gi] = 0.0f;       // h1 slots 0,1
        }
        for (int i = gi; i < 4099 * 64; i += NCTA * NTHR) {
            int row = i >> 6, b = i & 63;
            g_yT[row][b] = (row < 3) ? -100.0f : y[b * T_STEPS + (row - 3)];
        }
    }

    // ======== init: smem weights (plain fp32 rows) ========
    // local row r = gate*2 + lj ; global row = gate*256 + j0 + lj
    for (int idx = tid; idx < 8 * 256; idx += NTHR) {
        int r = idx >> 8, m = idx & 255;
        int row = (r >> 1) * 256 + j0 + (r & 1);
        W0s[idx] = Whh0[row * 256 + m];
        W1s[idx] = Wih1[row * 256 + m];
        WHs[idx] = Whh1[row * 256 + m];
    }
    if (tid < 8) {
        int row = (tid >> 1) * 256 + j0 + (tid & 1);
        b0s[tid] = bih0[row] + bhh0[row];
        b1s[tid] = bih1[row] + bhh1[row];
        for (int k = 0; k < 4; k++) wih0[tid * 4 + k] = Wih0[row * 4 + k];
    }
    wout[tid] = Wout[tid];                   // exactly 512 elements
    if (tid < 2) bo2[tid] = bout[tid];
    grid_barrier(tid, ls);   // round 1

    // ======== persistent 2-layer LSTM ========
    const int q    = tid >> 5;               // warp id = m-chunk (16 m per chunk)
    const int lane = tid & 31;                // batch pair: batches 2*lane, 2*lane+1
    const float* W0r = W0s + q * 16;          // + r*256 + mp2*4
    const float* W1r = W1s + q * 16;
    const float* WHr = WHs + q * 16;
    const int hfl = q * 8 * 128 + 4 * lane;   // float offset of thread's first K-pair

    // cell-update role (first 256 threads; c lives in a register)
    const int clb   = tid & 63;
    const int clj   = (tid >> 6) & 1;
    const int chalf = (tid >> 7) & 1;         // 0: layer0 cell, 1: layer1 cell
    float creg = 0.0f;

    for (int p = 0; p <= T_STEPS; p++) {
        const float* H0 = &g_h0[(p + 1) & 1][0][0][0] + hfl;  // h0(p-1)
        const float* H1 = &g_h1[p][0][0][0] + hfl;            // h1(p-2)
        if (tid < 256 && p < T_STEPS) yw[tid] = g_yT[p + (tid >> 6)][tid & 63];

        // h registers: [i].x = batch0 K-pair, [i].y = batch1 K-pair (mp = q*8+i)
        ulonglong2 h0r[8], h1r[8];
        #pragma unroll
        for (int i = 0; i < 8; i++) h0r[i] = ldcg2(H0 + i * 128);
        #pragma unroll
        for (int i = 0; i < 8; i++) h1r[i] = ldcg2(H1 + i * 128);

        // ---- layer0: 8 rows x 16 m x 2 batches ----
        {
            ull aA[8], aB[8];
            #pragma unroll
            for (int r = 0; r < 8; r++) { aA[r] = 0ull; aB[r] = 0ull; }
            #pragma unroll
            for (int mp2 = 0; mp2 < 4; mp2++) {
                const ulonglong2 hE = h0r[2 * mp2], hO = h0r[2 * mp2 + 1];
                #pragma unroll
                for (int r = 0; r < 8; r++) {
                    ulonglong2 wv = *(const ulonglong2*)(W0r + r * 256 + mp2 * 4);
                    aA[r] = ffma2(hE.x, wv.x, aA[r]);
                    aB[r] = ffma2(hE.y, wv.x, aB[r]);
                    aA[r] = ffma2(hO.x, wv.y, aA[r]);
                    aB[r] = ffma2(hO.y, wv.y, aB[r]);
                }
            }
            #pragma unroll
            for (int r = 0; r < 8; r++) {
                float2 v = make_float2(collapse2(aA[r]), collapse2(aB[r]));
                *(float2*)(P0 + q * 512 + r * 64 + 2 * lane) = v;
            }
        }
        // ---- layer1: W_ih1 x h0(p-1) + W_hh1 x h1(p-2) ----
        {
            ull aA[8], aB[8];
            #pragma unroll
            for (int r = 0; r < 8; r++) { aA[r] = 0ull; aB[r] = 0ull; }
            #pragma unroll
            for (int mp2 = 0; mp2 < 4; mp2++) {
                const ulonglong2 hE = h0r[2 * mp2], hO = h0r[2 * mp2 + 1];
                #pragma unroll
                for (int r = 0; r < 8; r++) {
                    ulonglong2 wv = *(const ulonglong2*)(W1r + r * 256 + mp2 * 4);
                    aA[r] = ffma2(hE.x, wv.x, aA[r]);
                    aB[r] = ffma2(hE.y, wv.x, aB[r]);
                    aA[r] = ffma2(hO.x, wv.y, aA[r]);
                    aB[r] = ffma2(hO.y, wv.y, aB[r]);
                }
            }
            #pragma unroll
            for (int mp2 = 0; mp2 < 4; mp2++) {
                const ulonglong2 hE = h1r[2 * mp2], hO = h1r[2 * mp2 + 1];
                #pragma unroll
                for (int r = 0; r < 8; r++) {
                    ulonglong2 wv = *(const ulonglong2*)(WHr + r * 256 + mp2 * 4);
                    aA[r] = ffma2(hE.x, wv.x, aA[r]);
                    aB[r] = ffma2(hE.y, wv.x, aB[r]);
                    aA[r] = ffma2(hO.x, wv.y, aA[r]);
                    aB[r] = ffma2(hO.y, wv.y, aB[r]);
                }
            }
            #pragma unroll
            for (int r = 0; r < 8; r++) {
                float2 v = make_float2(collapse2(aA[r]), collapse2(aB[r]));
                *(float2*)(P1 + q * 512 + r * 64 + 2 * lane) = v;
            }
        }
        __syncthreads();

        // ---- reduce 16 q-partials, cell update, publish h (first 256 threads) ----
        if (tid < 256) {
            const bool act = chalf ? (p > 0) : (p < T_STEPS);
            if (act) {
                const float* P  = chalf ? P1 : P0;
                const float* bs = chalf ? b1s : b0s;
                float gg[4];
                #pragma unroll
                for (int gt = 0; gt < 4; gt++) {
                    int r = gt * 2 + clj;
                    float s = bs[r];
                    #pragma unroll
                    for (int qq = 0; qq < 16; qq++)
                        s += P[qq * 512 + r * 64 + clb];
                    gg[gt] = s;
                }
                if (chalf == 0) {
                    #pragma unroll
                    for (int gt = 0; gt < 4; gt++) {
                        int r = gt * 2 + clj;
                        #pragma unroll
                        for (int k = 0; k < 4; k++)
                            gg[gt] = fmaf(yw[k * 64 + clb], wih0[r * 4 + k], gg[gt]);
                    }
                }
                creg = sigf(gg[1]) * creg + sigf(gg[0]) * tanh_f(gg[2]);
                float h = sigf(gg[3]) * tanh_f(creg);
                int j = j0 + clj;
                if (chalf == 0) g_h0[p & 1][j >> 1][clb][j & 1] = h;   // h0(p)
                else            g_h1[p + 1][j >> 1][clb][j & 1] = h;   // h1(p-1)
            }
        }
        grid_barrier(tid, ls);   // rounds 2..4098 (even total)
    }

    // ======== output projection: out[b][t][k] = h1(t).Wout[k] + bout[k] ========
    {
        const int b  = tid & 63;
        const int tt = tid >> 6;    // 0..7
        #pragma unroll
        for (int u = 0; u < 4; u++) {
            int t = bid * 32 + tt * 4 + u;
            const float* h = &g_h1[t + 2][0][0][0] + b * 2;
            float s0 = bo2[0], s1 = bo2[1];
            #pragma unroll 8
            for (int mp = 0; mp < 128; mp++) {
                float2 v = *(const float2*)(h + mp * 128);
                s0 = fmaf(v.x, wout[2 * mp],       s0);
                s0 = fmaf(v.y, wout[2 * mp + 1],   s0);
                s1 = fmaf(v.x, wout[256 + 2 * mp], s1);
                s1 = fmaf(v.y, wout[257 + 2 * mp], s1);
            }
            out[b * (T_STEPS * 2) + t * 2 + 0] = s0;
            out[b * (T_STEPS * 2) + t * 2 + 1] = s1;
        }
    }
}

// ---------------- launcher: ONE kernel ----------------
extern "C" void kernel_launch(void* const* d_in, const int* in_sizes, int n_in,
                              void* d_out, int out_size)
{
    (void)in_sizes; (void)n_in; (void)out_size;
    cudaFuncSetAttribute(lstm_all, cudaFuncAttributeMaxDynamicSharedMemorySize, SMEM_BYTES);
    lstm_all<<<NCTA, NTHR, SMEM_BYTES>>>(
        (const float*)d_in[0],
        (const float*)d_in[1], (const float*)d_in[2],
        (const float*)d_in[3], (const float*)d_in[4],
        (const float*)d_in[5], (const float*)d_in[6],
        (const float*)d_in[7], (const float*)d_in[8],
        (const float*)d_in[9], (const float*)d_in[10],
        (float*)d_out);
}